// round 14
// baseline (speedup 1.0000x reference)
#include <cuda_runtime.h>
#include <cuda_fp16.h>
#include <cstdint>

#define TILE_E   160
#define NTHREADS 640
#define N_NODES_MAX 50000

// smem layout in 4-byte words
#define W1F    0        // 16384 : W1 fragment-major fp16 (64 KB)
#define XH_F   16384    // 20480 : fp16 X (160 rows x 128 half2 words), cp.async target (80 KB)
#define H1_F   36864    // 10240 : fp16 h1 (160 rows x 64 half2 words) (40 KB)
#define PART_F 47104    // 640 floats
#define SMEM_W 47744    // * 4 = 190976 B

__device__ __align__(16) __half g_w2h[128 * 64];                 // W2 fragment-major fp16
__device__ __align__(16) __half g_zh[(size_t)N_NODES_MAX * 128]; // z pre-quantized fp16

__device__ __forceinline__ uint32_t smem_u32(const void* p) {
    uint32_t a; asm("{ .reg .u64 t; cvta.to.shared.u64 t, %1; cvt.u32.u64 %0, t; }" : "=r"(a) : "l"(p));
    return a;
}
__device__ __forceinline__ void mma_f16(float c[4],
    uint32_t a0, uint32_t a1, uint32_t a2, uint32_t a3, uint32_t b0, uint32_t b1)
{
    asm volatile("mma.sync.aligned.m16n8k16.row.col.f32.f16.f16.f32 "
        "{%0,%1,%2,%3}, {%4,%5,%6,%7}, {%8,%9}, {%0,%1,%2,%3};"
        : "+f"(c[0]), "+f"(c[1]), "+f"(c[2]), "+f"(c[3])
        : "r"(a0), "r"(a1), "r"(a2), "r"(a3), "r"(b0), "r"(b1));
}
__device__ __forceinline__ void ldsm_x4(uint32_t& r0, uint32_t& r1, uint32_t& r2, uint32_t& r3,
                                        uint32_t addr)
{
    asm volatile("ldmatrix.sync.aligned.m8n8.x4.shared.b16 {%0,%1,%2,%3}, [%4];"
        : "=r"(r0), "=r"(r1), "=r"(r2), "=r"(r3) : "r"(addr));
}
__device__ __forceinline__ void cpa16(uint32_t s, const void* g) {
    asm volatile("cp.async.cg.shared.global [%0], [%1], 16;" :: "r"(s), "l"(g));
}
#define CPA_COMMIT() asm volatile("cp.async.commit_group;" ::: "memory")
#define CPA_WAIT(n)  asm volatile("cp.async.wait_group %0;" :: "n"(n) : "memory")

__device__ __forceinline__ uint32_t packh2(float lo, float hi) {
    __half2 h = __floats2half2_rn(lo, hi);
    return *reinterpret_cast<uint32_t*>(&h);
}

// merged setup: W2 repack + z quantization
__global__ void prep(const float* __restrict__ z, const float* __restrict__ W2, int npairs) {
    int i = blockIdx.x * blockDim.x + threadIdx.x;
    if (i < 128 * 64) {
        int k = i >> 6, m = i & 63;
        int kk = k >> 4, klo = k & 15, half = klo >> 3, tgk = (klo >> 1) & 3, h = klo & 1;
        int nq = m >> 4, ntl = (m >> 3) & 1, ng = m & 7;
        int f4 = (kk * 4 + nq) * 32 + ng * 4 + tgk;
        g_w2h[f4 * 8 + ntl * 4 + half * 2 + h] = __float2half_rn(__ldg(W2 + i));
    }
    if (i < npairs) {
        float2 v = __ldg((const float2*)z + i);
        reinterpret_cast<__half2*>(g_zh)[i] = __floats2half2_rn(v.x, v.y);
    }
}

extern __shared__ float smem[];

__global__ void __launch_bounds__(NTHREADS, 1) lp_tc(
    const int*   __restrict__ ei,
    const float* __restrict__ W1,
    const float* __restrict__ b1,
    const float* __restrict__ b2,
    const float* __restrict__ W3,
    const float* __restrict__ b3,
    float* __restrict__ out,
    int E, int n_nodes, int ntiles)
{
    const int tid  = threadIdx.x;
    const int lane = tid & 31;
    const int wid  = tid >> 5;
    const int tg   = lane & 3;
    const int g    = lane >> 2;
    uint32_t* s32 = reinterpret_cast<uint32_t*>(smem);
    float* part = smem + PART_F;
    const uint32_t smb = smem_u32(smem);

    // ---- one-time: W1 -> smem fragment-major fp16 ----
    {
        __half* w1h = reinterpret_cast<__half*>(s32 + W1F);
        for (int i = tid; i < 256 * 128; i += NTHREADS) {
            int k = i >> 7, n = i & 127;
            int kk = k >> 4, klo = k & 15, half = klo >> 3, tgk = (klo >> 1) & 3, h = klo & 1;
            int nqq = n >> 5, ntl = (n >> 3) & 3, ng = n & 7;
            int f4 = ((kk * 4 + nqq) * 2 + (ntl >> 1)) * 32 + ng * 4 + tgk;
            w1h[f4 * 8 + (ntl & 1) * 4 + half * 2 + h] = __float2half_rn(__ldg(W1 + i));
        }
    }

    // warp roles: 20 warps = 5 M-groups (32 edges) x 4 N-quarters
    const int wm  = wid >> 2;
    const int nq  = wid & 3;
    const int base = wm * 32;
    const int nb1 = nq * 32;
    const int nb2 = nq * 16;

    float b1f[4][2], b2f[2][2], w3f[2][2];
    #pragma unroll
    for (int nt = 0; nt < 4; nt++) {
        b1f[nt][0] = __ldg(b1 + nb1 + nt * 8 + 2 * tg);
        b1f[nt][1] = __ldg(b1 + nb1 + nt * 8 + 2 * tg + 1);
    }
    #pragma unroll
    for (int nt = 0; nt < 2; nt++) {
        b2f[nt][0] = __ldg(b2 + nb2 + nt * 8 + 2 * tg);
        b2f[nt][1] = __ldg(b2 + nb2 + nt * 8 + 2 * tg + 1);
        w3f[nt][0] = __ldg(W3 + nb2 + nt * 8 + 2 * tg);
        w3f[nt][1] = __ldg(W3 + nb2 + nt * 8 + 2 * tg + 1);
    }
    const float b3v = __ldg(b3);

    // ldmatrix A-address bases: rows base+(lane&15) and base+16+(lane&15)
    const int arow0 = base + (lane & 15);
    const int acb   = (lane >> 4) * 4;          // k word offset sub-selector
    const int aswz  = (lane & 7) << 2;          // row swizzle (row&7 == lane&7 here)
    const uint32_t aX0 = smb + (XH_F + arow0 * 128) * 4;
    const uint32_t aX1 = smb + (XH_F + (arow0 + 16) * 128) * 4;
    const uint32_t aH0 = smb + (H1_F + arow0 * 64) * 4;
    const uint32_t aH1 = smb + (H1_F + (arow0 + 16) * 64) * 4;

    // gather role: 4 threads per edge; per stage each stages 16 halves (2 chunks)
    const int ge  = tid >> 2;
    const int gq  = tid & 3;
    const int gsw = (ge & 7) << 2;

    uint32_t* h1 = s32 + H1_F;

    int csrc = 0, cdst = 0;
    {
        long long eid = (long long)blockIdx.x * TILE_E + ge;
        if (eid >= (long long)E) eid = (long long)E - 1;
        csrc = min(max(__ldg(ei + eid), 0), n_nodes - 1);
        cdst = min(max(__ldg(ei + (long long)E + eid), 0), n_nodes - 1);
    }
    __syncthreads();   // W1 repack visible before first MMA

    // stage s: 0=src lo64, 1=src hi64, 2=dst lo64, 3=dst hi64 (halves)
    auto issue = [&](int s, int src, int dst) {
        const int node = (s < 2) ? src : dst;
        const __half* gp = g_zh + (size_t)node * 128 + (s & 1) * 64 + gq * 16;
        #pragma unroll
        for (int j = 0; j < 2; j++)
            cpa16(smb + (XH_F + ge * 128 + ((s * 32 + gq * 8 + j * 4) ^ gsw)) * 4, gp + j * 8);
    };
    auto issue_all = [&](int src, int dst) {
        issue(0, src, dst); issue(1, src, dst); issue(2, src, dst); issue(3, src, dst);
    };

    // prologue: entire first tile in ONE commit group
    issue_all(csrc, cdst);
    CPA_COMMIT();

    for (int tile = blockIdx.x; tile < ntiles; tile += gridDim.x) {
        const long long e0 = (long long)tile * TILE_E;
        const int tn = tile + gridDim.x;
        const bool hn = tn < ntiles;

        // prefetch next tile's indices into registers (overlaps layer 1)
        int nsrc = 0, ndst = 0;
        if (hn) {
            long long eid = (long long)tn * TILE_E + ge;
            if (eid >= (long long)E) eid = (long long)E - 1;
            nsrc = min(max(__ldg(ei + eid), 0), n_nodes - 1);
            ndst = min(max(__ldg(ei + (long long)E + eid), 0), n_nodes - 1);
        }

        float acc[2][4][4];
        #pragma unroll
        for (int mt = 0; mt < 2; mt++)
            #pragma unroll
            for (int nt = 0; nt < 4; nt++)
                #pragma unroll
                for (int q = 0; q < 4; q++) acc[mt][nt][q] = 0.f;

        CPA_WAIT(0); __syncthreads();        // whole X tile resident

        // ---- layer 1: 16 uninterrupted k16-steps ----
        #pragma unroll 4
        for (int kk = 0; kk < 16; kk++) {
            const int k0 = kk * 8;
            const uint32_t aoff = (uint32_t)(((k0 + acb) ^ aswz) << 2);
            uint32_t a[2][4];
            ldsm_x4(a[0][0], a[0][1], a[0][2], a[0][3], aX0 + aoff);
            ldsm_x4(a[1][0], a[1][1], a[1][2], a[1][3], aX1 + aoff);
            const uint4 bfA = *reinterpret_cast<const uint4*>(
                s32 + W1F + ((((kk * 4 + nq) * 2 + 0) * 32) + lane) * 4);
            const uint4 bfB = *reinterpret_cast<const uint4*>(
                s32 + W1F + ((((kk * 4 + nq) * 2 + 1) * 32) + lane) * 4);
            #pragma unroll
            for (int mt = 0; mt < 2; mt++) {
                mma_f16(acc[mt][0], a[mt][0], a[mt][1], a[mt][2], a[mt][3], bfA.x, bfA.y);
                mma_f16(acc[mt][1], a[mt][0], a[mt][1], a[mt][2], a[mt][3], bfA.z, bfA.w);
                mma_f16(acc[mt][2], a[mt][0], a[mt][1], a[mt][2], a[mt][3], bfB.x, bfB.y);
                mma_f16(acc[mt][3], a[mt][0], a[mt][1], a[mt][2], a[mt][3], bfB.z, bfB.w);
            }
        }
        __syncthreads();                     // all XH reads done

        // issue entire next tile (one commit group) — epilogue hides the gather
        if (hn) issue_all(nsrc, ndst);
        CPA_COMMIT();

        // ---- h1 = fp16(relu(acc + b1)) -> H1 (row stride 64 words) ----
        #pragma unroll
        for (int mt = 0; mt < 2; mt++) {
            const int rw1 = (base + mt * 16 + g) * 64;
            const int rw2 = (base + mt * 16 + g + 8) * 64;
            #pragma unroll
            for (int nt = 0; nt < 4; nt++) {
                const int j = (nq * 16 + nt * 4 + tg) ^ (g << 2);
                h1[rw1 + j] = packh2(fmaxf(acc[mt][nt][0] + b1f[nt][0], 0.f),
                                     fmaxf(acc[mt][nt][1] + b1f[nt][1], 0.f));
                h1[rw2 + j] = packh2(fmaxf(acc[mt][nt][2] + b1f[nt][0], 0.f),
                                     fmaxf(acc[mt][nt][3] + b1f[nt][1], 0.f));
            }
        }
        __syncthreads();

        // ---- layer 2: C[32 x 16] = H1 @ W2, K=128 (8 k16-steps) ----
        float acc2[2][2][4];
        #pragma unroll
        for (int mt = 0; mt < 2; mt++)
            #pragma unroll
            for (int nt = 0; nt < 2; nt++)
                #pragma unroll
                for (int q = 0; q < 4; q++) acc2[mt][nt][q] = 0.f;
        #pragma unroll 4
        for (int kk = 0; kk < 8; kk++) {
            const int k0 = kk * 8;
            const uint32_t aoff = (uint32_t)(((k0 + acb) ^ aswz) << 2);
            uint32_t a[2][4];
            ldsm_x4(a[0][0], a[0][1], a[0][2], a[0][3], aH0 + aoff);
            ldsm_x4(a[1][0], a[1][1], a[1][2], a[1][3], aH1 + aoff);
            const uint4 bf = __ldg(reinterpret_cast<const uint4*>(
                reinterpret_cast<const uint32_t*>(g_w2h) + (((kk * 4 + nq) * 32) + lane) * 4));
            #pragma unroll
            for (int mt = 0; mt < 2; mt++) {
                mma_f16(acc2[mt][0], a[mt][0], a[mt][1], a[mt][2], a[mt][3], bf.x, bf.y);
                mma_f16(acc2[mt][1], a[mt][0], a[mt][1], a[mt][2], a[mt][3], bf.z, bf.w);
            }
        }

        // ---- layer 3: dot with W3, shfl reduce over tg, combine ----
        #pragma unroll
        for (int mt = 0; mt < 2; mt++) {
            float p0 = 0.f, p1 = 0.f;
            #pragma unroll
            for (int nt = 0; nt < 2; nt++) {
                p0 += fmaxf(acc2[mt][nt][0] + b2f[nt][0], 0.f) * w3f[nt][0]
                    + fmaxf(acc2[mt][nt][1] + b2f[nt][1], 0.f) * w3f[nt][1];
                p1 += fmaxf(acc2[mt][nt][2] + b2f[nt][0], 0.f) * w3f[nt][0]
                    + fmaxf(acc2[mt][nt][3] + b2f[nt][1], 0.f) * w3f[nt][1];
            }
            p0 += __shfl_xor_sync(0xffffffffu, p0, 1);
            p0 += __shfl_xor_sync(0xffffffffu, p0, 2);
            p1 += __shfl_xor_sync(0xffffffffu, p1, 1);
            p1 += __shfl_xor_sync(0xffffffffu, p1, 2);
            if (tg == 0) {
                part[(base + mt * 16 + g) * 4 + nq]     = p0;
                part[(base + mt * 16 + g + 8) * 4 + nq] = p1;
            }
        }
        __syncthreads();

        if (tid < TILE_E) {
            long long eid = e0 + tid;
            if (eid < (long long)E)
                out[eid] = part[tid * 4] + part[tid * 4 + 1]
                         + part[tid * 4 + 2] + part[tid * 4 + 3] + b3v;
        }
        csrc = nsrc; cdst = ndst;
        // next write to part is behind the loop-top wait barrier.
    }
}

extern "C" void kernel_launch(void* const* d_in, const int* in_sizes, int n_in,
                              void* d_out, int out_size)
{
    const float* z  = (const float*)d_in[0];
    const int*   ei = (const int*)d_in[1];
    const float* W1 = (const float*)d_in[2];
    const float* b1 = (const float*)d_in[3];
    const float* W2 = (const float*)d_in[4];
    const float* b2 = (const float*)d_in[5];
    const float* W3 = (const float*)d_in[6];
    const float* b3 = (const float*)d_in[7];
    float* out = (float*)d_out;

    const int E       = in_sizes[1] / 2;
    int n_nodes       = in_sizes[0] / 128;
    if (n_nodes > N_NODES_MAX) n_nodes = N_NODES_MAX;
    const int ntiles  = (E + TILE_E - 1) / TILE_E;
    const int smem_bytes = SMEM_W * 4;   // 190976 B

    static bool attr_set = false;
    if (!attr_set) {
        cudaFuncSetAttribute(lp_tc, cudaFuncAttributeMaxDynamicSharedMemorySize, smem_bytes);
        attr_set = true;
    }

    const int npairs = n_nodes * 64;
    const int prep_n = (npairs > 128 * 64) ? npairs : 128 * 64;
    prep<<<(prep_n + 255) / 256, 256>>>(z, W2, npairs);

    int grid = 148;
    if (grid > ntiles) grid = ntiles;
    lp_tc<<<grid, NTHREADS, smem_bytes>>>(ei, W1, b1, b2, W3, b3, out, E, n_nodes, ntiles);
}

// round 15
// speedup vs baseline: 1.2290x; 1.2290x over previous
#include <cuda_runtime.h>
#include <cuda_fp16.h>
#include <cstdint>

#define TILE_E   160
#define NTHREADS 640
#define N_NODES_MAX 50000

// smem layout in 4-byte words
#define W1F    0        // 16384 : W1 fragment-major fp16 (64 KB)
#define XH_F   16384    // 20480 : fp16 X (160 rows x 128 half2 words), cp.async target (80 KB)
#define H1_F   36864    // 10240 : fp16 h1 (160 rows x 64 half2 words) (40 KB)
#define PART_F 47104    // 640 floats
#define SMEM_W 47744    // * 4 = 190976 B

__device__ __align__(16) __half g_w2h[128 * 64];                 // W2 fragment-major fp16
__device__ __align__(16) __half g_zh[(size_t)N_NODES_MAX * 128]; // z pre-quantized fp16

__device__ __forceinline__ uint32_t smem_u32(const void* p) {
    uint32_t a; asm("{ .reg .u64 t; cvta.to.shared.u64 t, %1; cvt.u32.u64 %0, t; }" : "=r"(a) : "l"(p));
    return a;
}
__device__ __forceinline__ void mma_f16(float c[4],
    uint32_t a0, uint32_t a1, uint32_t a2, uint32_t a3, uint32_t b0, uint32_t b1)
{
    asm volatile("mma.sync.aligned.m16n8k16.row.col.f32.f16.f16.f32 "
        "{%0,%1,%2,%3}, {%4,%5,%6,%7}, {%8,%9}, {%0,%1,%2,%3};"
        : "+f"(c[0]), "+f"(c[1]), "+f"(c[2]), "+f"(c[3])
        : "r"(a0), "r"(a1), "r"(a2), "r"(a3), "r"(b0), "r"(b1));
}
__device__ __forceinline__ void ldsm_x4(uint32_t& r0, uint32_t& r1, uint32_t& r2, uint32_t& r3,
                                        uint32_t addr)
{
    asm volatile("ldmatrix.sync.aligned.m8n8.x4.shared.b16 {%0,%1,%2,%3}, [%4];"
        : "=r"(r0), "=r"(r1), "=r"(r2), "=r"(r3) : "r"(addr));
}
__device__ __forceinline__ void cpa16(uint32_t s, const void* g) {
    asm volatile("cp.async.cg.shared.global [%0], [%1], 16;" :: "r"(s), "l"(g));
}
#define CPA_COMMIT() asm volatile("cp.async.commit_group;" ::: "memory")
#define CPA_WAIT(n)  asm volatile("cp.async.wait_group %0;" :: "n"(n) : "memory")
// group-scoped barrier: 4 warps (128 threads) of M-group wm, barrier id wm+1
#define GBAR(wm) asm volatile("bar.sync %0, 128;" :: "r"((wm) + 1) : "memory")

__device__ __forceinline__ uint32_t packh2(float lo, float hi) {
    __half2 h = __floats2half2_rn(lo, hi);
    return *reinterpret_cast<uint32_t*>(&h);
}

// merged setup: W2 repack + z quantization
__global__ void prep(const float* __restrict__ z, const float* __restrict__ W2, int npairs) {
    int i = blockIdx.x * blockDim.x + threadIdx.x;
    if (i < 128 * 64) {
        int k = i >> 6, m = i & 63;
        int kk = k >> 4, klo = k & 15, half = klo >> 3, tgk = (klo >> 1) & 3, h = klo & 1;
        int nq = m >> 4, ntl = (m >> 3) & 1, ng = m & 7;
        int f4 = (kk * 4 + nq) * 32 + ng * 4 + tgk;
        g_w2h[f4 * 8 + ntl * 4 + half * 2 + h] = __float2half_rn(__ldg(W2 + i));
    }
    if (i < npairs) {
        float2 v = __ldg((const float2*)z + i);
        reinterpret_cast<__half2*>(g_zh)[i] = __floats2half2_rn(v.x, v.y);
    }
}

extern __shared__ float smem[];

__global__ void __launch_bounds__(NTHREADS, 1) lp_tc(
    const int*   __restrict__ ei,
    const float* __restrict__ W1,
    const float* __restrict__ b1,
    const float* __restrict__ b2,
    const float* __restrict__ W3,
    const float* __restrict__ b3,
    float* __restrict__ out,
    int E, int n_nodes, int ntiles)
{
    const int tid  = threadIdx.x;
    const int lane = tid & 31;
    const int tg   = lane & 3;
    const int g    = lane >> 2;
    const int gtid = tid & 127;        // thread within warpgroup
    const int wm   = tid >> 7;         // M-group 0..4 (owns edges base..base+31)
    const int nq   = (tid >> 5) & 3;   // N-quarter within group
    const int base = wm * 32;
    uint32_t* s32 = reinterpret_cast<uint32_t*>(smem);
    float* part = smem + PART_F;
    const uint32_t smb = smem_u32(smem);

    // ---- one-time: W1 -> smem fragment-major fp16 ----
    {
        __half* w1h = reinterpret_cast<__half*>(s32 + W1F);
        for (int i = tid; i < 256 * 128; i += NTHREADS) {
            int k = i >> 7, n = i & 127;
            int kk = k >> 4, klo = k & 15, half = klo >> 3, tgk = (klo >> 1) & 3, h = klo & 1;
            int nqq = n >> 5, ntl = (n >> 3) & 3, ng = n & 7;
            int f4 = ((kk * 4 + nqq) * 2 + (ntl >> 1)) * 32 + ng * 4 + tgk;
            w1h[f4 * 8 + (ntl & 1) * 4 + half * 2 + h] = __float2half_rn(__ldg(W1 + i));
        }
    }

    const int nb1 = nq * 32;
    const int nb2 = nq * 16;

    float b1f[4][2], b2f[2][2], w3f[2][2];
    #pragma unroll
    for (int nt = 0; nt < 4; nt++) {
        b1f[nt][0] = __ldg(b1 + nb1 + nt * 8 + 2 * tg);
        b1f[nt][1] = __ldg(b1 + nb1 + nt * 8 + 2 * tg + 1);
    }
    #pragma unroll
    for (int nt = 0; nt < 2; nt++) {
        b2f[nt][0] = __ldg(b2 + nb2 + nt * 8 + 2 * tg);
        b2f[nt][1] = __ldg(b2 + nb2 + nt * 8 + 2 * tg + 1);
        w3f[nt][0] = __ldg(W3 + nb2 + nt * 8 + 2 * tg);
        w3f[nt][1] = __ldg(W3 + nb2 + nt * 8 + 2 * tg + 1);
    }
    const float b3v = __ldg(b3);

    // ldmatrix A-address bases (rows within own group's 32-row band)
    const int arow0 = base + (lane & 15);
    const int acb   = (lane >> 4) * 4;
    const int aswz  = (lane & 7) << 2;
    const uint32_t aX0 = smb + (XH_F + arow0 * 128) * 4;
    const uint32_t aX1 = smb + (XH_F + (arow0 + 16) * 128) * 4;
    const uint32_t aH0 = smb + (H1_F + arow0 * 64) * 4;
    const uint32_t aH1 = smb + (H1_F + (arow0 + 16) * 64) * 4;

    // gather role (GROUP-LOCAL): 4 threads per edge over the group's 32 edges
    const int ge  = base + (gtid >> 2);   // edge row 0..159 owned by this thread
    const int gq  = gtid & 3;
    const int gsw = (ge & 7) << 2;

    uint32_t* h1 = s32 + H1_F;

    int csrc = 0, cdst = 0;
    {
        long long eid = (long long)blockIdx.x * TILE_E + ge;
        if (eid >= (long long)E) eid = (long long)E - 1;
        csrc = min(max(__ldg(ei + eid), 0), n_nodes - 1);
        cdst = min(max(__ldg(ei + (long long)E + eid), 0), n_nodes - 1);
    }
    __syncthreads();   // only block-wide sync: W1 repack visible

    auto issue_all = [&](int src, int dst) {
        #pragma unroll
        for (int s = 0; s < 4; s++) {
            const int node = (s < 2) ? src : dst;
            const __half* gp = g_zh + (size_t)node * 128 + (s & 1) * 64 + gq * 16;
            #pragma unroll
            for (int j = 0; j < 2; j++)
                cpa16(smb + (XH_F + ge * 128 + ((s * 32 + gq * 8 + j * 4) ^ gsw)) * 4, gp + j * 8);
        }
    };

    // prologue: first tile's gather (one commit group)
    issue_all(csrc, cdst);
    CPA_COMMIT();

    for (int tile = blockIdx.x; tile < ntiles; tile += gridDim.x) {
        const long long e0 = (long long)tile * TILE_E;
        const int tn = tile + gridDim.x;
        const bool hn = tn < ntiles;

        // prefetch next tile's indices (overlaps layer 1)
        int nsrc = 0, ndst = 0;
        if (hn) {
            long long eid = (long long)tn * TILE_E + ge;
            if (eid >= (long long)E) eid = (long long)E - 1;
            nsrc = min(max(__ldg(ei + eid), 0), n_nodes - 1);
            ndst = min(max(__ldg(ei + (long long)E + eid), 0), n_nodes - 1);
        }

        float acc[2][4][4];
        #pragma unroll
        for (int mt = 0; mt < 2; mt++)
            #pragma unroll
            for (int nt = 0; nt < 4; nt++)
                #pragma unroll
                for (int q = 0; q < 4; q++) acc[mt][nt][q] = 0.f;

        CPA_WAIT(0);
        GBAR(wm);                        // group's X band resident

        // ---- layer 1: 16 uninterrupted k16-steps ----
        #pragma unroll 4
        for (int kk = 0; kk < 16; kk++) {
            const int k0 = kk * 8;
            const uint32_t aoff = (uint32_t)(((k0 + acb) ^ aswz) << 2);
            uint32_t a[2][4];
            ldsm_x4(a[0][0], a[0][1], a[0][2], a[0][3], aX0 + aoff);
            ldsm_x4(a[1][0], a[1][1], a[1][2], a[1][3], aX1 + aoff);
            const uint4 bfA = *reinterpret_cast<const uint4*>(
                s32 + W1F + ((((kk * 4 + nq) * 2 + 0) * 32) + lane) * 4);
            const uint4 bfB = *reinterpret_cast<const uint4*>(
                s32 + W1F + ((((kk * 4 + nq) * 2 + 1) * 32) + lane) * 4);
            #pragma unroll
            for (int mt = 0; mt < 2; mt++) {
                mma_f16(acc[mt][0], a[mt][0], a[mt][1], a[mt][2], a[mt][3], bfA.x, bfA.y);
                mma_f16(acc[mt][1], a[mt][0], a[mt][1], a[mt][2], a[mt][3], bfA.z, bfA.w);
                mma_f16(acc[mt][2], a[mt][0], a[mt][1], a[mt][2], a[mt][3], bfB.x, bfB.y);
                mma_f16(acc[mt][3], a[mt][0], a[mt][1], a[mt][2], a[mt][3], bfB.z, bfB.w);
            }
        }
        GBAR(wm);                        // group's X reads done

        // issue next tile's gather for this group (one commit group)
        if (hn) issue_all(nsrc, ndst);
        CPA_COMMIT();

        // ---- h1 = fp16(relu(acc + b1)) -> H1 band ----
        #pragma unroll
        for (int mt = 0; mt < 2; mt++) {
            const int rw1 = (base + mt * 16 + g) * 64;
            const int rw2 = (base + mt * 16 + g + 8) * 64;
            #pragma unroll
            for (int nt = 0; nt < 4; nt++) {
                const int j = (nq * 16 + nt * 4 + tg) ^ (g << 2);
                h1[rw1 + j] = packh2(fmaxf(acc[mt][nt][0] + b1f[nt][0], 0.f),
                                     fmaxf(acc[mt][nt][1] + b1f[nt][1], 0.f));
                h1[rw2 + j] = packh2(fmaxf(acc[mt][nt][2] + b1f[nt][0], 0.f),
                                     fmaxf(acc[mt][nt][3] + b1f[nt][1], 0.f));
            }
        }
        GBAR(wm);                        // group's h1 visible

        // ---- layer 2: C[32 x 16] = H1 @ W2, K=128 ----
        float acc2[2][2][4];
        #pragma unroll
        for (int mt = 0; mt < 2; mt++)
            #pragma unroll
            for (int nt = 0; nt < 2; nt++)
                #pragma unroll
                for (int q = 0; q < 4; q++) acc2[mt][nt][q] = 0.f;
        #pragma unroll 4
        for (int kk = 0; kk < 8; kk++) {
            const int k0 = kk * 8;
            const uint32_t aoff = (uint32_t)(((k0 + acb) ^ aswz) << 2);
            uint32_t a[2][4];
            ldsm_x4(a[0][0], a[0][1], a[0][2], a[0][3], aH0 + aoff);
            ldsm_x4(a[1][0], a[1][1], a[1][2], a[1][3], aH1 + aoff);
            const uint4 bf = __ldg(reinterpret_cast<const uint4*>(
                reinterpret_cast<const uint32_t*>(g_w2h) + (((kk * 4 + nq) * 32) + lane) * 4));
            #pragma unroll
            for (int mt = 0; mt < 2; mt++) {
                mma_f16(acc2[mt][0], a[mt][0], a[mt][1], a[mt][2], a[mt][3], bf.x, bf.y);
                mma_f16(acc2[mt][1], a[mt][0], a[mt][1], a[mt][2], a[mt][3], bf.z, bf.w);
            }
        }

        // ---- layer 3: dot with W3, shfl reduce over tg, combine ----
        #pragma unroll
        for (int mt = 0; mt < 2; mt++) {
            float p0 = 0.f, p1 = 0.f;
            #pragma unroll
            for (int nt = 0; nt < 2; nt++) {
                p0 += fmaxf(acc2[mt][nt][0] + b2f[nt][0], 0.f) * w3f[nt][0]
                    + fmaxf(acc2[mt][nt][1] + b2f[nt][1], 0.f) * w3f[nt][1];
                p1 += fmaxf(acc2[mt][nt][2] + b2f[nt][0], 0.f) * w3f[nt][0]
                    + fmaxf(acc2[mt][nt][3] + b2f[nt][1], 0.f) * w3f[nt][1];
            }
            p0 += __shfl_xor_sync(0xffffffffu, p0, 1);
            p0 += __shfl_xor_sync(0xffffffffu, p0, 2);
            p1 += __shfl_xor_sync(0xffffffffu, p1, 1);
            p1 += __shfl_xor_sync(0xffffffffu, p1, 2);
            if (tg == 0) {
                part[(base + mt * 16 + g) * 4 + nq]     = p0;
                part[(base + mt * 16 + g + 8) * 4 + nq] = p1;
            }
        }
        GBAR(wm);                        // group's part complete

        if (gtid < 32) {
            long long eid = e0 + base + gtid;
            if (eid < (long long)E)
                out[eid] = part[(base + gtid) * 4]     + part[(base + gtid) * 4 + 1]
                         + part[(base + gtid) * 4 + 2] + part[(base + gtid) * 4 + 3] + b3v;
        }
        csrc = nsrc; cdst = ndst;
        // part rewrite next tile is behind the loop-top GBARs of this group.
    }
}

extern "C" void kernel_launch(void* const* d_in, const int* in_sizes, int n_in,
                              void* d_out, int out_size)
{
    const float* z  = (const float*)d_in[0];
    const int*   ei = (const int*)d_in[1];
    const float* W1 = (const float*)d_in[2];
    const float* b1 = (const float*)d_in[3];
    const float* W2 = (const float*)d_in[4];
    const float* b2 = (const float*)d_in[5];
    const float* W3 = (const float*)d_in[6];
    const float* b3 = (const float*)d_in[7];
    float* out = (float*)d_out;

    const int E       = in_sizes[1] / 2;
    int n_nodes       = in_sizes[0] / 128;
    if (n_nodes > N_NODES_MAX) n_nodes = N_NODES_MAX;
    const int ntiles  = (E + TILE_E - 1) / TILE_E;
    const int smem_bytes = SMEM_W * 4;   // 190976 B

    static bool attr_set = false;
    if (!attr_set) {
        cudaFuncSetAttribute(lp_tc, cudaFuncAttributeMaxDynamicSharedMemorySize, smem_bytes);
        attr_set = true;
    }

    const int npairs = n_nodes * 64;
    const int prep_n = (npairs > 128 * 64) ? npairs : 128 * 64;
    prep<<<(prep_n + 255) / 256, 256>>>(z, W2, npairs);

    int grid = 148;
    if (grid > ntiles) grid = ntiles;
    lp_tc<<<grid, NTHREADS, smem_bytes>>>(ei, W1, b1, b2, W3, b3, out, E, n_nodes, ntiles);
}